// round 4
// baseline (speedup 1.0000x reference)
#include <cuda_runtime.h>
#include <cuda_bf16.h>

#define NUM_USERS 50000
#define NUM_ITEMS 50000
#define N_NODES   100000
#define HIDDEN    128
#define N_EDGES   1600000

// Scratch (static device globals; no runtime allocation)
__device__ float g_x  [N_NODES * HIDDEN];
__device__ float g_y  [N_NODES * HIDDEN];
__device__ float g_agg[N_NODES * HIDDEN];
__device__ float g_deg[N_NODES];

// ---------------------------------------------------------------------------
// init: x = concat(user_emb, item_emb); deg = 0
// ---------------------------------------------------------------------------
__global__ void k_init(const float4* __restrict__ ue, const float4* __restrict__ ie,
                       float4* __restrict__ x4, float* __restrict__ deg) {
    int i = blockIdx.x * blockDim.x + threadIdx.x;
    const int NU4 = NUM_USERS * HIDDEN / 4;   // 1.6M
    const int NT4 = N_NODES  * HIDDEN / 4;    // 3.2M
    if (i < NT4) {
        float4 v = (i < NU4) ? ue[i] : ie[i - NU4];
        x4[i] = v;
    }
    if (i < N_NODES) deg[i] = 0.0f;
}

// ---------------------------------------------------------------------------
// degree count (by dst)
// ---------------------------------------------------------------------------
__global__ void k_deg(const int* __restrict__ dst, float* __restrict__ deg) {
    int e = blockIdx.x * blockDim.x + threadIdx.x;
    if (e < N_EDGES) atomicAdd(&deg[dst[e]], 1.0f);
}

// ---------------------------------------------------------------------------
// zero agg
// ---------------------------------------------------------------------------
__global__ void k_zero_agg(float4* __restrict__ agg4) {
    int i = blockIdx.x * blockDim.x + threadIdx.x;
    if (i < N_NODES * HIDDEN / 4)
        agg4[i] = make_float4(0.f, 0.f, 0.f, 0.f);
}

// ---------------------------------------------------------------------------
// scatter: agg[dst] += x[src]   (one warp per edge, v4 reductions)
// ---------------------------------------------------------------------------
__global__ void k_scatter(const int* __restrict__ src, const int* __restrict__ dst,
                          const float* __restrict__ x, float* __restrict__ agg) {
    int t = blockIdx.x * blockDim.x + threadIdx.x;
    int e = t >> 5;
    int lane = t & 31;
    if (e < N_EDGES) {
        int s = src[e];
        int d = dst[e];
        float4 v = reinterpret_cast<const float4*>(x + (long)s * HIDDEN)[lane];
        float* p = agg + (long)d * HIDDEN + lane * 4;
        asm volatile("red.global.add.v4.f32 [%0], {%1, %2, %3, %4};"
                     :: "l"(p), "f"(v.x), "f"(v.y), "f"(v.z), "f"(v.w)
                     : "memory");
    }
}

// ---------------------------------------------------------------------------
// fused GEMM: out = relu([agg*inv_deg | x] @ W' + bl)
//   W'[k][j]     = Wl[j][k]   (k <  128)
//   W'[128+k][j] = Wr[j][k]   (k >= 128)
// block: 256 threads, 64 nodes x 128 cols; thread: 4 nodes x 8 cols
// ---------------------------------------------------------------------------
#define BNODES 64
#define LDW 129   // padded stride of sW (rows = k, 256 of them)
#define LDA 257   // padded stride of sA (rows = node, 64 of them)
#define GEMM_SMEM ((256 * LDW + BNODES * LDA + 128) * 4)

__global__ __launch_bounds__(256, 1)
void k_gemm(const float* __restrict__ xin, float* __restrict__ xout,
            const float* __restrict__ agg, const float* __restrict__ deg,
            const float* __restrict__ Wl, const float* __restrict__ Wr,
            const float* __restrict__ bl) {
    extern __shared__ float sm[];
    float* sW = sm;                      // [256][LDW]
    float* sA = sm + 256 * LDW;          // [BNODES][LDA] (256 used cols)
    float* sB = sA + BNODES * LDA;       // [128] bias

    const int tid = threadIdx.x;
    const int node0 = blockIdx.x * BNODES;

    // Load W' transposed into smem (padded stride -> conflict-free writes)
    for (int idx = tid; idx < 128 * 128; idx += 256) {
        int j = idx >> 7;
        int k = idx & 127;
        sW[k * LDW + j]         = Wl[idx];
        sW[(k + 128) * LDW + j] = Wr[idx];
    }
    if (tid < 128) sB[tid] = bl[tid];

    // Load A tile: [agg * inv_deg | x]
    for (int idx = tid; idx < BNODES * 128; idx += 256) {
        int n = idx >> 7;
        int k = idx & 127;
        int node = node0 + n;
        float a = 0.f, b = 0.f;
        if (node < N_NODES) {
            float inv = 1.0f / fmaxf(deg[node], 1.0f);
            a = agg[(long)node * HIDDEN + k] * inv;
            b = xin[(long)node * HIDDEN + k];
        }
        sA[n * LDA + k]       = a;
        sA[n * LDA + 128 + k] = b;
    }
    __syncthreads();

    const int tx = tid & 15;   // 16 col-groups
    const int ty = tid >> 4;   // 16 node-groups

    float acc[4][8];
#pragma unroll
    for (int i = 0; i < 4; i++)
#pragma unroll
        for (int j = 0; j < 8; j++) acc[i][j] = 0.f;

#pragma unroll 4
    for (int k = 0; k < 256; ++k) {
        float a[4], b[8];
#pragma unroll
        for (int i = 0; i < 4; i++) a[i] = sA[(ty * 4 + i) * LDA + k];
#pragma unroll
        for (int j = 0; j < 8; j++) b[j] = sW[k * LDW + tx + 16 * j];
#pragma unroll
        for (int i = 0; i < 4; i++)
#pragma unroll
            for (int j = 0; j < 8; j++) acc[i][j] += a[i] * b[j];
    }

    // Epilogue: bias + relu, cols c = tx + 16*j (coalesced 64B segments)
#pragma unroll
    for (int i = 0; i < 4; i++) {
        int node = node0 + ty * 4 + i;
        if (node < N_NODES) {
            float* orow = xout + (long)node * HIDDEN;
#pragma unroll
            for (int j = 0; j < 8; j++) {
                int c = tx + 16 * j;
                orow[c] = fmaxf(acc[i][j] + sB[c], 0.0f);
            }
        }
    }
}

// ---------------------------------------------------------------------------
// launch
// ---------------------------------------------------------------------------
extern "C" void kernel_launch(void* const* d_in, const int* in_sizes, int n_in,
                              void* d_out, int out_size) {
    const float* user_emb = (const float*)d_in[0];
    const float* item_emb = (const float*)d_in[1];
    const float* Wl       = (const float*)d_in[2];   // [2,128,128]
    const float* bl       = (const float*)d_in[3];   // [2,128]
    const float* Wr       = (const float*)d_in[4];   // [2,128,128]
    const int*   ei       = (const int*)  d_in[5];   // [2, N_EDGES]
    const int* src = ei;
    const int* dst = ei + N_EDGES;
    float* out = (float*)d_out;

    // CRITICAL: __device__ symbols must be resolved to device addresses before
    // being passed as kernel args from host code. (Passing the symbol directly
    // passes the host shadow address — which GB300's ATS happily dereferences,
    // silently reading host zeros.)
    float *px, *py, *pagg, *pdeg;
    cudaGetSymbolAddress((void**)&px,   g_x);
    cudaGetSymbolAddress((void**)&py,   g_y);
    cudaGetSymbolAddress((void**)&pagg, g_agg);
    cudaGetSymbolAddress((void**)&pdeg, g_deg);

    // Idempotent; safe to call every time (not a stream-capture op).
    cudaFuncSetAttribute(k_gemm, cudaFuncAttributeMaxDynamicSharedMemorySize,
                         GEMM_SMEM);

    const int T = 256;

    // init x and deg
    {
        int n = N_NODES * HIDDEN / 4;
        k_init<<<(n + T - 1) / T, T>>>((const float4*)user_emb,
                                       (const float4*)item_emb,
                                       (float4*)px, pdeg);
    }
    // degree
    k_deg<<<(N_EDGES + T - 1) / T, T>>>(dst, pdeg);

    const int gemm_blocks = (N_NODES + BNODES - 1) / BNODES;
    const int scat_threads = N_EDGES * 32;
    const int zero_blocks = (N_NODES * HIDDEN / 4 + T - 1) / T;
    const int scat_blocks = (scat_threads + T - 1) / T;

    // ---- layer 0: x -> y
    k_zero_agg<<<zero_blocks, T>>>((float4*)pagg);
    k_scatter<<<scat_blocks, T>>>(src, dst, px, pagg);
    k_gemm<<<gemm_blocks, T, GEMM_SMEM>>>(px, py, pagg, pdeg, Wl, Wr, bl);

    // ---- layer 1: y -> out
    k_zero_agg<<<zero_blocks, T>>>((float4*)pagg);
    k_scatter<<<scat_blocks, T>>>(src, dst, py, pagg);
    k_gemm<<<gemm_blocks, T, GEMM_SMEM>>>(py, out, pagg, pdeg,
                                          Wl + 128 * 128, Wr + 128 * 128,
                                          bl + 128);
}

// round 7
// speedup vs baseline: 1.5428x; 1.5428x over previous
#include <cuda_runtime.h>
#include <cuda_bf16.h>

#define NUM_USERS 50000
#define NUM_ITEMS 50000
#define N_NODES   100000
#define HIDDEN    128
#define N_EDGES   1600000

// Scratch (static device globals; no runtime allocation)
__device__ float g_x   [N_NODES * HIDDEN];
__device__ float g_y   [N_NODES * HIDDEN];
__device__ float g_agg [N_NODES * HIDDEN];
__device__ int   g_degi[N_NODES];
__device__ int   g_off [N_NODES + 1];
__device__ int   g_cur [N_NODES];
__device__ int   g_slot[N_EDGES];

// ---------------------------------------------------------------------------
// init: x = concat(user_emb, item_emb); degi = 0
// ---------------------------------------------------------------------------
__global__ void k_init(const float4* __restrict__ ue, const float4* __restrict__ ie,
                       float4* __restrict__ x4, int* __restrict__ degi) {
    int i = blockIdx.x * blockDim.x + threadIdx.x;
    const int NU4 = NUM_USERS * HIDDEN / 4;
    const int NT4 = N_NODES  * HIDDEN / 4;
    if (i < NT4) {
        float4 v = (i < NU4) ? ue[i] : ie[i - NU4];
        x4[i] = v;
    }
    if (i < N_NODES) degi[i] = 0;
}

// ---------------------------------------------------------------------------
// degree count (by dst)
// ---------------------------------------------------------------------------
__global__ void k_deg(const int* __restrict__ dst, int* __restrict__ degi) {
    int e = blockIdx.x * blockDim.x + threadIdx.x;
    if (e < N_EDGES) atomicAdd(&degi[dst[e]], 1);
}

// ---------------------------------------------------------------------------
// exclusive scan over degrees -> CSR offsets (single block, 1024 threads)
// ---------------------------------------------------------------------------
#define SCAN_T 1024
#define SCAN_CH ((N_NODES + SCAN_T - 1) / SCAN_T)   // 98

__global__ __launch_bounds__(SCAN_T)
void k_scan(const int* __restrict__ degi, int* __restrict__ off,
            int* __restrict__ cur) {
    __shared__ int sh[SCAN_T];
    int t = threadIdx.x;
    int base = t * SCAN_CH;
    int s = 0;
#pragma unroll 4
    for (int i = 0; i < SCAN_CH; i++) {
        int n = base + i;
        if (n < N_NODES) s += degi[n];
    }
    sh[t] = s;
    __syncthreads();
    // Hillis-Steele inclusive scan
    for (int d = 1; d < SCAN_T; d <<= 1) {
        int v = (t >= d) ? sh[t - d] : 0;
        __syncthreads();
        sh[t] += v;
        __syncthreads();
    }
    int run = sh[t] - s;   // exclusive prefix for this chunk
    for (int i = 0; i < SCAN_CH; i++) {
        int n = base + i;
        if (n < N_NODES) {
            off[n] = run;
            cur[n] = run;
            run += degi[n];
        }
    }
    if (t == SCAN_T - 1) off[N_NODES] = sh[SCAN_T - 1];
}

// ---------------------------------------------------------------------------
// fill CSR slots:  slot[cur[dst]++] = src
// ---------------------------------------------------------------------------
__global__ void k_fill(const int* __restrict__ src, const int* __restrict__ dst,
                       int* __restrict__ cur, int* __restrict__ slot) {
    int e = blockIdx.x * blockDim.x + threadIdx.x;
    if (e < N_EDGES) {
        int p = atomicAdd(&cur[dst[e]], 1);
        slot[p] = src[e];
    }
}

// ---------------------------------------------------------------------------
// aggregate: agg[n] = inv_deg * sum_{e in adj(n)} x[slot[e]]
// one warp per node; lane owns one float4 (4 of 128 features)
// ---------------------------------------------------------------------------
__global__ void k_aggregate(const int* __restrict__ off, const int* __restrict__ slot,
                            const float* __restrict__ x, float* __restrict__ agg) {
    int t = blockIdx.x * blockDim.x + threadIdx.x;
    int node = t >> 5;
    int lane = t & 31;
    if (node >= N_NODES) return;
    int b = off[node];
    int e = off[node + 1];
    float4 acc = make_float4(0.f, 0.f, 0.f, 0.f);
    int i = b;
    // unroll by 2 for memory-level parallelism
    for (; i + 1 < e; i += 2) {
        int s0 = slot[i];
        int s1 = slot[i + 1];
        float4 v0 = reinterpret_cast<const float4*>(x + (long)s0 * HIDDEN)[lane];
        float4 v1 = reinterpret_cast<const float4*>(x + (long)s1 * HIDDEN)[lane];
        acc.x += v0.x; acc.y += v0.y; acc.z += v0.z; acc.w += v0.w;
        acc.x += v1.x; acc.y += v1.y; acc.z += v1.z; acc.w += v1.w;
    }
    if (i < e) {
        int s0 = slot[i];
        float4 v0 = reinterpret_cast<const float4*>(x + (long)s0 * HIDDEN)[lane];
        acc.x += v0.x; acc.y += v0.y; acc.z += v0.z; acc.w += v0.w;
    }
    int cnt = e - b;
    float inv = 1.0f / (float)max(cnt, 1);
    acc.x *= inv; acc.y *= inv; acc.z *= inv; acc.w *= inv;
    reinterpret_cast<float4*>(agg + (long)node * HIDDEN)[lane] = acc;
}

// ---------------------------------------------------------------------------
// fused GEMM: out = relu([agg | x] @ W' + bl)       (agg already deg-scaled)
//   W'[k][j]     = Wl[j][k]   (k <  128)
//   W'[128+k][j] = Wr[j][k]   (k >= 128)
// block: 256 threads, 64 nodes x 128 cols; thread: 4 nodes x 8 cols
// thread cols: tx*4..tx*4+3 and 64+tx*4..64+tx*4+3 (two LDS.128 per k)
// ---------------------------------------------------------------------------
#define BNODES 64
#define LDW 132   // padded stride of sW (mult of 4 for float4 alignment)
#define LDA 260   // padded stride of sA (mult of 4)
#define GEMM_SMEM ((256 * LDW + BNODES * LDA + 128) * 4)

__global__ __launch_bounds__(256, 1)
void k_gemm(const float* __restrict__ xin, float* __restrict__ xout,
            const float* __restrict__ agg,
            const float* __restrict__ Wl, const float* __restrict__ Wr,
            const float* __restrict__ bl) {
    extern __shared__ float sm[];
    float* sW = sm;                      // [256][LDW]
    float* sA = sm + 256 * LDW;          // [BNODES][LDA]
    float* sB = sA + BNODES * LDA;       // [128] bias

    const int tid = threadIdx.x;
    const int node0 = blockIdx.x * BNODES;

    // Load W' transposed into smem
    for (int idx = tid; idx < 128 * 128; idx += 256) {
        int j = idx >> 7;
        int k = idx & 127;
        sW[k * LDW + j]         = Wl[idx];
        sW[(k + 128) * LDW + j] = Wr[idx];
    }
    if (tid < 128) sB[tid] = bl[tid];

    // Load A tile with float4: [agg | x],  64 nodes x 256 k
    for (int idx = tid; idx < BNODES * 32; idx += 256) {
        int n  = idx >> 5;
        int kq = idx & 31;
        int node = node0 + n;
        float4 a = make_float4(0.f, 0.f, 0.f, 0.f);
        float4 b = a;
        if (node < N_NODES) {
            a = reinterpret_cast<const float4*>(agg + (long)node * HIDDEN)[kq];
            b = reinterpret_cast<const float4*>(xin + (long)node * HIDDEN)[kq];
        }
        *reinterpret_cast<float4*>(&sA[n * LDA + kq * 4])       = a;
        *reinterpret_cast<float4*>(&sA[n * LDA + 128 + kq * 4]) = b;
    }
    __syncthreads();

    const int tx = tid & 15;   // 16 col-groups (cols tx*4 and 64+tx*4)
    const int ty = tid >> 4;   // 16 node-groups

    float acc[4][8];
#pragma unroll
    for (int i = 0; i < 4; i++)
#pragma unroll
        for (int j = 0; j < 8; j++) acc[i][j] = 0.f;

#pragma unroll 4
    for (int k = 0; k < 256; ++k) {
        float a[4];
#pragma unroll
        for (int i = 0; i < 4; i++) a[i] = sA[(ty * 4 + i) * LDA + k];
        float4 b0 = *reinterpret_cast<const float4*>(&sW[k * LDW + tx * 4]);
        float4 b1 = *reinterpret_cast<const float4*>(&sW[k * LDW + 64 + tx * 4]);
#pragma unroll
        for (int i = 0; i < 4; i++) {
            acc[i][0] += a[i] * b0.x; acc[i][1] += a[i] * b0.y;
            acc[i][2] += a[i] * b0.z; acc[i][3] += a[i] * b0.w;
            acc[i][4] += a[i] * b1.x; acc[i][5] += a[i] * b1.y;
            acc[i][6] += a[i] * b1.z; acc[i][7] += a[i] * b1.w;
        }
    }

    // Epilogue: bias + relu, two float4 stores per node row
    float4 bb0 = *reinterpret_cast<const float4*>(&sB[tx * 4]);
    float4 bb1 = *reinterpret_cast<const float4*>(&sB[64 + tx * 4]);
#pragma unroll
    for (int i = 0; i < 4; i++) {
        int node = node0 + ty * 4 + i;
        if (node < N_NODES) {
            float* orow = xout + (long)node * HIDDEN;
            float4 o0, o1;
            o0.x = fmaxf(acc[i][0] + bb0.x, 0.f);
            o0.y = fmaxf(acc[i][1] + bb0.y, 0.f);
            o0.z = fmaxf(acc[i][2] + bb0.z, 0.f);
            o0.w = fmaxf(acc[i][3] + bb0.w, 0.f);
            o1.x = fmaxf(acc[i][4] + bb1.x, 0.f);
            o1.y = fmaxf(acc[i][5] + bb1.y, 0.f);
            o1.z = fmaxf(acc[i][6] + bb1.z, 0.f);
            o1.w = fmaxf(acc[i][7] + bb1.w, 0.f);
            *reinterpret_cast<float4*>(orow + tx * 4)      = o0;
            *reinterpret_cast<float4*>(orow + 64 + tx * 4) = o1;
        }
    }
}

// ---------------------------------------------------------------------------
// launch
// ---------------------------------------------------------------------------
extern "C" void kernel_launch(void* const* d_in, const int* in_sizes, int n_in,
                              void* d_out, int out_size) {
    const float* user_emb = (const float*)d_in[0];
    const float* item_emb = (const float*)d_in[1];
    const float* Wl       = (const float*)d_in[2];   // [2,128,128]
    const float* bl       = (const float*)d_in[3];   // [2,128]
    const float* Wr       = (const float*)d_in[4];   // [2,128,128]
    const int*   ei       = (const int*)  d_in[5];   // [2, N_EDGES]
    const int* src = ei;
    const int* dst = ei + N_EDGES;
    float* out = (float*)d_out;

    // Resolve __device__ symbols to device addresses (ATS would silently
    // dereference the host shadow otherwise).
    float *px, *py, *pagg;
    int *pdegi, *poff, *pcur, *pslot;
    cudaGetSymbolAddress((void**)&px,    g_x);
    cudaGetSymbolAddress((void**)&py,    g_y);
    cudaGetSymbolAddress((void**)&pagg,  g_agg);
    cudaGetSymbolAddress((void**)&pdegi, g_degi);
    cudaGetSymbolAddress((void**)&poff,  g_off);
    cudaGetSymbolAddress((void**)&pcur,  g_cur);
    cudaGetSymbolAddress((void**)&pslot, g_slot);

    cudaFuncSetAttribute(k_gemm, cudaFuncAttributeMaxDynamicSharedMemorySize,
                         GEMM_SMEM);

    const int T = 256;

    // init x and degi
    {
        int n = N_NODES * HIDDEN / 4;
        k_init<<<(n + T - 1) / T, T>>>((const float4*)user_emb,
                                       (const float4*)item_emb,
                                       (float4*)px, pdegi);
    }
    k_deg<<<(N_EDGES + T - 1) / T, T>>>(dst, pdegi);
    k_scan<<<1, SCAN_T>>>(pdegi, poff, pcur);
    k_fill<<<(N_EDGES + T - 1) / T, T>>>(src, dst, pcur, pslot);

    const int gemm_blocks = (N_NODES + BNODES - 1) / BNODES;
    const int agg_blocks  = (N_NODES * 32 + T - 1) / T;

    // ---- layer 0: x -> y
    k_aggregate<<<agg_blocks, T>>>(poff, pslot, px, pagg);
    k_gemm<<<gemm_blocks, T, GEMM_SMEM>>>(px, py, pagg, Wl, Wr, bl);

    // ---- layer 1: y -> out
    k_aggregate<<<agg_blocks, T>>>(poff, pslot, py, pagg);
    k_gemm<<<gemm_blocks, T, GEMM_SMEM>>>(py, out, pagg,
                                          Wl + 128 * 128, Wr + 128 * 128,
                                          bl + 128);
}

// round 10
// speedup vs baseline: 1.7386x; 1.1269x over previous
#include <cuda_runtime.h>
#include <cuda_bf16.h>

#define NUM_USERS 50000
#define NUM_ITEMS 50000
#define N_NODES   100000
#define HIDDEN    128
#define N_EDGES   1600000

typedef unsigned long long ull;

// Scratch (static device globals; no runtime allocation)
__device__ float g_x   [N_NODES * HIDDEN];
__device__ float g_y   [N_NODES * HIDDEN];
__device__ float g_agg [N_NODES * HIDDEN];
__device__ int   g_degi[N_NODES];
__device__ int   g_off [N_NODES + 1];
__device__ int   g_cur [N_NODES];
__device__ int   g_slot[N_EDGES];

// ---------------------------------------------------------------------------
__global__ void k_init(const float4* __restrict__ ue, const float4* __restrict__ ie,
                       float4* __restrict__ x4, int* __restrict__ degi) {
    int i = blockIdx.x * blockDim.x + threadIdx.x;
    const int NU4 = NUM_USERS * HIDDEN / 4;
    const int NT4 = N_NODES  * HIDDEN / 4;
    if (i < NT4) {
        float4 v = (i < NU4) ? ue[i] : ie[i - NU4];
        x4[i] = v;
    }
    if (i < N_NODES) degi[i] = 0;
}

__global__ void k_deg(const int* __restrict__ dst, int* __restrict__ degi) {
    int e = blockIdx.x * blockDim.x + threadIdx.x;
    if (e < N_EDGES) atomicAdd(&degi[dst[e]], 1);
}

// ---------------------------------------------------------------------------
#define SCAN_T 1024
#define SCAN_CH ((N_NODES + SCAN_T - 1) / SCAN_T)

__global__ __launch_bounds__(SCAN_T)
void k_scan(const int* __restrict__ degi, int* __restrict__ off,
            int* __restrict__ cur) {
    __shared__ int sh[SCAN_T];
    int t = threadIdx.x;
    int base = t * SCAN_CH;
    int s = 0;
#pragma unroll 4
    for (int i = 0; i < SCAN_CH; i++) {
        int n = base + i;
        if (n < N_NODES) s += degi[n];
    }
    sh[t] = s;
    __syncthreads();
    for (int d = 1; d < SCAN_T; d <<= 1) {
        int v = (t >= d) ? sh[t - d] : 0;
        __syncthreads();
        sh[t] += v;
        __syncthreads();
    }
    int run = sh[t] - s;
    for (int i = 0; i < SCAN_CH; i++) {
        int n = base + i;
        if (n < N_NODES) {
            off[n] = run;
            cur[n] = run;
            run += degi[n];
        }
    }
    if (t == SCAN_T - 1) off[N_NODES] = sh[SCAN_T - 1];
}

__global__ void k_fill(const int* __restrict__ src, const int* __restrict__ dst,
                       int* __restrict__ cur, int* __restrict__ slot) {
    int e = blockIdx.x * blockDim.x + threadIdx.x;
    if (e < N_EDGES) {
        int p = atomicAdd(&cur[dst[e]], 1);
        slot[p] = src[e];
    }
}

// ---------------------------------------------------------------------------
// aggregate: agg[n] = inv_deg * sum x[slot[e]]; one warp/node, float4 lanes
// ---------------------------------------------------------------------------
__global__ void k_aggregate(const int* __restrict__ off, const int* __restrict__ slot,
                            const float* __restrict__ x, float* __restrict__ agg) {
    int t = blockIdx.x * blockDim.x + threadIdx.x;
    int node = t >> 5;
    int lane = t & 31;
    if (node >= N_NODES) return;
    int b = off[node];
    int e = off[node + 1];
    float4 acc = make_float4(0.f, 0.f, 0.f, 0.f);
    int i = b;
    for (; i + 3 < e; i += 4) {
        int s0 = slot[i], s1 = slot[i+1], s2 = slot[i+2], s3 = slot[i+3];
        float4 v0 = reinterpret_cast<const float4*>(x + (long)s0 * HIDDEN)[lane];
        float4 v1 = reinterpret_cast<const float4*>(x + (long)s1 * HIDDEN)[lane];
        float4 v2 = reinterpret_cast<const float4*>(x + (long)s2 * HIDDEN)[lane];
        float4 v3 = reinterpret_cast<const float4*>(x + (long)s3 * HIDDEN)[lane];
        acc.x += v0.x + v1.x + v2.x + v3.x;
        acc.y += v0.y + v1.y + v2.y + v3.y;
        acc.z += v0.z + v1.z + v2.z + v3.z;
        acc.w += v0.w + v1.w + v2.w + v3.w;
    }
    for (; i < e; i++) {
        int s0 = slot[i];
        float4 v0 = reinterpret_cast<const float4*>(x + (long)s0 * HIDDEN)[lane];
        acc.x += v0.x; acc.y += v0.y; acc.z += v0.z; acc.w += v0.w;
    }
    int cnt = e - b;
    float inv = 1.0f / (float)max(cnt, 1);
    acc.x *= inv; acc.y *= inv; acc.z *= inv; acc.w *= inv;
    reinterpret_cast<float4*>(agg + (long)node * HIDDEN)[lane] = acc;
}

// ---------------------------------------------------------------------------
// fused GEMM with packed f32x2 FMA (sm_103a FFMA2):
//   out = relu([agg | x] @ W' + bl)     (agg pre-scaled by inv_deg)
// block: 256 threads, tile 128 nodes x 128 cols; thread: 8 nodes x 8 cols
// K=256 processed as 2 chunks of 128 (chunk0 = agg, chunk1 = x);
// sA is k-major so a-operands are broadcast LDS.128.
// ---------------------------------------------------------------------------
#define BNODES 128
#define LDW 132            // sW stride (floats), 16B-aligned rows
#define SAN 132            // sA stride (floats), 16B-aligned rows
#define GEMM_SMEM ((256 * LDW + 128 * SAN + 128) * 4)

#define FFMA2(acc, A, B) \
    asm("fma.rn.f32x2 %0, %1, %2, %3;" : "=l"(acc) : "l"(A), "l"(B), "l"(acc))

__device__ __forceinline__ ull pk2(float v) {
    ull r;
    unsigned u = __float_as_uint(v);
    asm("mov.b64 %0, {%1, %1};" : "=l"(r) : "r"(u));
    return r;
}
__device__ __forceinline__ float2 upk2(ull v) {
    unsigned lo, hi;
    asm("mov.b64 {%0, %1}, %2;" : "=r"(lo), "=r"(hi) : "l"(v));
    return make_float2(__uint_as_float(lo), __uint_as_float(hi));
}

__global__ __launch_bounds__(256, 1)
void k_gemm(const float* __restrict__ xin, float* __restrict__ xout,
            const float* __restrict__ agg,
            const float* __restrict__ Wl, const float* __restrict__ Wr,
            const float* __restrict__ bl) {
    extern __shared__ float sm[];
    float* sW = sm;                    // [256][LDW]  W'[k][j]
    float* sA = sm + 256 * LDW;        // [128][SAN]  k-major chunk
    float* sB = sA + 128 * SAN;        // [128] bias

    const int tid = threadIdx.x;
    const int node0 = blockIdx.x * BNODES;

    // Load W' transposed (coalesced global reads; ~4-way STS conflict, prologue only)
    for (int idx = tid; idx < 128 * 128; idx += 256) {
        int j = idx >> 7;
        int k = idx & 127;
        sW[k * LDW + j]         = Wl[idx];
        sW[(k + 128) * LDW + j] = Wr[idx];
    }
    if (tid < 128) sB[tid] = bl[tid];

    const int tx = tid & 15;   // cols tx*4..+3 and 64+tx*4..+3
    const int ty = tid >> 4;   // nodes ty*8..+7

    ull acc2[8][4];
#pragma unroll
    for (int i = 0; i < 8; i++)
#pragma unroll
        for (int j = 0; j < 4; j++) acc2[i][j] = 0ULL;

#pragma unroll
    for (int chunk = 0; chunk < 2; chunk++) {
        const float* srcmat = chunk ? xin : agg;
        __syncthreads();   // chunk1: wait until all readers of previous sA done
        // fill sA k-major: sA[k][n] = srcmat[node0+n][k]
        // lanes iterate n (conflict-free STS); global reads 16B/lane gather (L2)
        for (int idx = tid; idx < BNODES * 32; idx += 256) {
            int n  = idx & 127;
            int kq = idx >> 7;
            int node = node0 + n;
            float4 v = make_float4(0.f, 0.f, 0.f, 0.f);
            if (node < N_NODES)
                v = reinterpret_cast<const float4*>(srcmat + (long)node * HIDDEN)[kq];
            sA[(kq * 4 + 0) * SAN + n] = v.x;
            sA[(kq * 4 + 1) * SAN + n] = v.y;
            sA[(kq * 4 + 2) * SAN + n] = v.z;
            sA[(kq * 4 + 3) * SAN + n] = v.w;
        }
        __syncthreads();

        const int kw0 = chunk * 128;
#pragma unroll 4
        for (int k = 0; k < 128; ++k) {
            // a: 8 node values (broadcast LDS.128 x2)
            float4 a0 = *reinterpret_cast<const float4*>(&sA[k * SAN + ty * 8]);
            float4 a1 = *reinterpret_cast<const float4*>(&sA[k * SAN + ty * 8 + 4]);
            // b: 8 col values as 4 packed f32x2 (native pairs, no packing)
            ulonglong2 b01 = *reinterpret_cast<const ulonglong2*>(&sW[(kw0 + k) * LDW + tx * 4]);
            ulonglong2 b23 = *reinterpret_cast<const ulonglong2*>(&sW[(kw0 + k) * LDW + 64 + tx * 4]);
            float av[8] = {a0.x, a0.y, a0.z, a0.w, a1.x, a1.y, a1.z, a1.w};
#pragma unroll
            for (int i = 0; i < 8; i++) {
                ull A = pk2(av[i]);
                FFMA2(acc2[i][0], A, b01.x);
                FFMA2(acc2[i][1], A, b01.y);
                FFMA2(acc2[i][2], A, b23.x);
                FFMA2(acc2[i][3], A, b23.y);
            }
        }
    }

    // Epilogue: bias + relu, two float4 stores per node row
    float4 bb0 = *reinterpret_cast<const float4*>(&sB[tx * 4]);
    float4 bb1 = *reinterpret_cast<const float4*>(&sB[64 + tx * 4]);
#pragma unroll
    for (int i = 0; i < 8; i++) {
        int node = node0 + ty * 8 + i;
        if (node < N_NODES) {
            float* orow = xout + (long)node * HIDDEN;
            float2 p0 = upk2(acc2[i][0]);
            float2 p1 = upk2(acc2[i][1]);
            float2 p2 = upk2(acc2[i][2]);
            float2 p3 = upk2(acc2[i][3]);
            float4 o0, o1;
            o0.x = fmaxf(p0.x + bb0.x, 0.f);
            o0.y = fmaxf(p0.y + bb0.y, 0.f);
            o0.z = fmaxf(p1.x + bb0.z, 0.f);
            o0.w = fmaxf(p1.y + bb0.w, 0.f);
            o1.x = fmaxf(p2.x + bb1.x, 0.f);
            o1.y = fmaxf(p2.y + bb1.y, 0.f);
            o1.z = fmaxf(p3.x + bb1.z, 0.f);
            o1.w = fmaxf(p3.y + bb1.w, 0.f);
            *reinterpret_cast<float4*>(orow + tx * 4)      = o0;
            *reinterpret_cast<float4*>(orow + 64 + tx * 4) = o1;
        }
    }
}

// ---------------------------------------------------------------------------
extern "C" void kernel_launch(void* const* d_in, const int* in_sizes, int n_in,
                              void* d_out, int out_size) {
    const float* user_emb = (const float*)d_in[0];
    const float* item_emb = (const float*)d_in[1];
    const float* Wl       = (const float*)d_in[2];   // [2,128,128]
    const float* bl       = (const float*)d_in[3];   // [2,128]
    const float* Wr       = (const float*)d_in[4];   // [2,128,128]
    const int*   ei       = (const int*)  d_in[5];   // [2, N_EDGES]
    const int* src = ei;
    const int* dst = ei + N_EDGES;
    float* out = (float*)d_out;

    // Resolve __device__ symbols to device addresses (ATS would silently
    // dereference the host shadow otherwise).
    float *px, *py, *pagg;
    int *pdegi, *poff, *pcur, *pslot;
    cudaGetSymbolAddress((void**)&px,    g_x);
    cudaGetSymbolAddress((void**)&py,    g_y);
    cudaGetSymbolAddress((void**)&pagg,  g_agg);
    cudaGetSymbolAddress((void**)&pdegi, g_degi);
    cudaGetSymbolAddress((void**)&poff,  g_off);
    cudaGetSymbolAddress((void**)&pcur,  g_cur);
    cudaGetSymbolAddress((void**)&pslot, g_slot);

    cudaFuncSetAttribute(k_gemm, cudaFuncAttributeMaxDynamicSharedMemorySize,
                         GEMM_SMEM);

    const int T = 256;

    {
        int n = N_NODES * HIDDEN / 4;
        k_init<<<(n + T - 1) / T, T>>>((const float4*)user_emb,
                                       (const float4*)item_emb,
                                       (float4*)px, pdegi);
    }
    k_deg<<<(N_EDGES + T - 1) / T, T>>>(dst, pdegi);
    k_scan<<<1, SCAN_T>>>(pdegi, poff, pcur);
    k_fill<<<(N_EDGES + T - 1) / T, T>>>(src, dst, pcur, pslot);

    const int gemm_blocks = (N_NODES + BNODES - 1) / BNODES;   // 782
    const int agg_blocks  = (N_NODES * 32 + T - 1) / T;

    // ---- layer 0: x -> y
    k_aggregate<<<agg_blocks, T>>>(poff, pslot, px, pagg);
    k_gemm<<<gemm_blocks, T, GEMM_SMEM>>>(px, py, pagg, Wl, Wr, bl);

    // ---- layer 1: y -> out
    k_aggregate<<<agg_blocks, T>>>(poff, pslot, py, pagg);
    k_gemm<<<gemm_blocks, T, GEMM_SMEM>>>(py, out, pagg,
                                          Wl + 128 * 128, Wr + 128 * 128,
                                          bl + 128);
}